// round 5
// baseline (speedup 1.0000x reference)
#include <cuda_runtime.h>
#include <math.h>

#define NN 30000
#define EE 480000
#define FIN 128
#define DD 32
#define HH 4
#define HD 128
#define GG 128
#define TT 10

// ---------------- scratch (device globals; no allocation allowed) ----------------
__device__ float g_xlr[NN*256];     // per node: [0:128)=xl, [128:256)=xr
__device__ float g_hfeat[NN*DD];
__device__ int   g_src[EE];
__device__ int   g_dst[EE];
__device__ int   g_csr_src[EE];
__device__ int   g_deg[NN];
__device__ int   g_fill[NN];
__device__ int   g_rowptr[NN+1];
__device__ int   g_batch[NN];
__device__ float g_pool[GG*DD];

// float atomic max via sign-split (correct incl. -0.0; init = -inf)
__device__ __forceinline__ void atomicMaxF(float* addr, float v) {
  unsigned u = __float_as_uint(v);
  if (u >> 31) atomicMin((unsigned*)addr, u);
  else         atomicMax((int*)addr, (int)u);
}

// ---------------- prep: dtype-agnostic index conversion + init ----------------
__global__ void k_prep(const void* __restrict__ ei, const void* __restrict__ bt) {
  __shared__ int s64;
  if (threadIdx.x == 0) {
    const long long* p = (const long long*)ei;
    int ok = 1;
    #pragma unroll
    for (int i = 0; i < 16; i++) { long long v = p[i]; if (v < 0 || v >= NN) ok = 0; }
    s64 = ok;
  }
  __syncthreads();
  int is64 = s64;
  int i = blockIdx.x*blockDim.x + threadIdx.x;
  if (i < EE) {
    if (is64) {
      const long long* p = (const long long*)ei;
      g_src[i] = (int)p[i]; g_dst[i] = (int)p[EE + i];
    } else {
      const int* p = (const int*)ei;
      g_src[i] = p[i]; g_dst[i] = p[EE + i];
    }
  }
  if (i < NN) {
    g_batch[i] = is64 ? (int)((const long long*)bt)[i] : ((const int*)bt)[i];
    g_deg[i] = 0;
  }
  if (i < GG*DD) g_pool[i] = -INFINITY;
}

__global__ void k_count() {
  int i = blockIdx.x*blockDim.x + threadIdx.x;
  if (i < EE) atomicAdd(&g_deg[g_dst[i]], 1);
}

// single-block exclusive scan over g_deg -> g_rowptr (and seed g_fill = rowptr)
__global__ __launch_bounds__(1024) void k_scan() {
  __shared__ int ssum[1024];
  const int per = (NN + 1023)/1024;  // 30
  int t = threadIdx.x;
  int base = t*per;
  int vals[32];
  int local = 0;
  for (int i = 0; i < per; i++) {
    int idx = base + i;
    int v = (idx < NN) ? g_deg[idx] : 0;
    vals[i] = local; local += v;
  }
  ssum[t] = local;
  __syncthreads();
  for (int off = 1; off < 1024; off <<= 1) {
    int v = (t >= off) ? ssum[t-off] : 0;
    __syncthreads();
    ssum[t] += v;
    __syncthreads();
  }
  int prev = (t == 0) ? 0 : ssum[t-1];
  for (int i = 0; i < per; i++) {
    int idx = base + i;
    if (idx < NN) { int rp = prev + vals[i]; g_rowptr[idx] = rp; g_fill[idx] = rp; }
  }
  if (t == 1023) g_rowptr[NN] = ssum[1023];
}

__global__ void k_fill() {
  int i = blockIdx.x*blockDim.x + threadIdx.x;
  if (i >= EE) return;
  int pos = atomicAdd(&g_fill[g_dst[i]], 1);
  g_csr_src[pos] = g_src[i];
}

// ---------------- dual SGEMM: C[m][0:128)=A@Wl^T+bl, C[m][128:256)=A@Wr^T+br ----------------
// BM=128, BN=128 (of combined 256), BK=16, 256 threads, 8x8 microtile.
__global__ __launch_bounds__(256) void k_dualgemm(
    const float* __restrict__ A,
    const float* __restrict__ Wl, const float* __restrict__ bl,
    const float* __restrict__ Wr, const float* __restrict__ br,
    float* __restrict__ C, int M, int K) {
  __shared__ float As[16][132];
  __shared__ float Bs[16][132];
  const int bm = blockIdx.y * 128;
  const int bn = blockIdx.x * 128;       // 0 or 128 of combined 256
  const int tid = threadIdx.x;
  const int tr = tid >> 4;               // 0..15 -> rows tr*8..+8
  const int tc = tid & 15;               // 0..15 -> cols tc*8..+8
  float acc[8][8] = {};
  for (int k0 = 0; k0 < K; k0 += 16) {
    #pragma unroll
    for (int i = 0; i < 2; i++) {
      int li = tid + i*256;              // 0..511 -> 128 rows x 4 float4
      int r = li >> 2;
      int kk = (li & 3) * 4;
      int m = bm + r;
      float4 v = make_float4(0.f,0.f,0.f,0.f);
      if (m < M) v = *(const float4*)&A[(size_t)m*K + k0 + kk];
      As[kk+0][r] = v.x; As[kk+1][r] = v.y; As[kk+2][r] = v.z; As[kk+3][r] = v.w;
    }
    #pragma unroll
    for (int i = 0; i < 2; i++) {
      int li = tid + i*256;
      int r = li >> 2;
      int kk = (li & 3) * 4;
      int n = bn + r;
      const float* Wrow = (n < 128) ? &Wl[(size_t)n*K] : &Wr[(size_t)(n-128)*K];
      float4 v = *(const float4*)&Wrow[k0 + kk];
      Bs[kk+0][r] = v.x; Bs[kk+1][r] = v.y; Bs[kk+2][r] = v.z; Bs[kk+3][r] = v.w;
    }
    __syncthreads();
    #pragma unroll
    for (int k = 0; k < 16; k++) {
      float4 a0 = *(const float4*)&As[k][tr*8];
      float4 a1 = *(const float4*)&As[k][tr*8 + 4];
      float4 b0 = *(const float4*)&Bs[k][tc*8];
      float4 b1 = *(const float4*)&Bs[k][tc*8 + 4];
      float a[8] = {a0.x,a0.y,a0.z,a0.w,a1.x,a1.y,a1.z,a1.w};
      float b[8] = {b0.x,b0.y,b0.z,b0.w,b1.x,b1.y,b1.z,b1.w};
      #pragma unroll
      for (int i = 0; i < 8; i++)
        #pragma unroll
        for (int j = 0; j < 8; j++) acc[i][j] += a[i]*b[j];
    }
    __syncthreads();
  }
  float bia[8];
  #pragma unroll
  for (int j = 0; j < 8; j++) {
    int n = bn + tc*8 + j;
    bia[j] = (n < 128) ? bl[n] : br[n-128];
  }
  #pragma unroll
  for (int i = 0; i < 8; i++) {
    int m = bm + tr*8 + i;
    if (m >= M) continue;
    float4 o0 = make_float4(acc[i][0]+bia[0], acc[i][1]+bia[1], acc[i][2]+bia[2], acc[i][3]+bia[3]);
    float4 o1 = make_float4(acc[i][4]+bia[4], acc[i][5]+bia[5], acc[i][6]+bia[6], acc[i][7]+bia[7]);
    *(float4*)&C[(size_t)m*256 + bn + tc*8]     = o0;
    *(float4*)&C[(size_t)m*256 + bn + tc*8 + 4] = o1;
  }
}

// ---------------- fused GATv2: edge gather + softmax + mean-agg + Linear(HD->DD) ----------------
// one block (128 thr = 4 warps) per dst node; software-pipelined edge loop.
__global__ __launch_bounds__(128) void k_conv_fused(
    const float* __restrict__ att, const float* __restrict__ cb,
    const float* __restrict__ lw, const float* __restrict__ lb,
    float* __restrict__ outp, int do_pool) {
  int d = blockIdx.x;
  int t = threadIdx.x;
  int w = t >> 5, lane = t & 31;
  __shared__ float sacc[4][HD];
  __shared__ float sden[4][32];
  __shared__ float tmp[HD];
  __shared__ float spo[HD];

  float4 xr4 = *(const float4*)&g_xlr[(size_t)d*256 + 128 + lane*4];
  float4 at4 = *(const float4*)&att[lane*4];
  float4 acc = make_float4(0.f,0.f,0.f,0.f);
  float den = 0.f;
  int rs = g_rowptr[d], re = g_rowptr[d+1];

  int pos = rs + w;
  int end = re + 1;                       // re == implicit self loop
  float4 xv_p;
  if (pos < end) {
    int s0 = (pos < re) ? g_csr_src[pos] : d;
    xv_p = *(const float4*)&g_xlr[(size_t)s0*256 + lane*4];
  }
  for (; pos < end; pos += 4) {
    float4 xv = xv_p;
    int pn = pos + 4;
    if (pn < end) {                       // prefetch next edge's features
      int sn = (pn < re) ? g_csr_src[pn] : d;
      xv_p = *(const float4*)&g_xlr[(size_t)sn*256 + lane*4];
    }
    float v0 = xv.x + xr4.x; v0 = (v0 > 0.f ? v0 : 0.2f*v0) * at4.x;
    float v1 = xv.y + xr4.y; v1 = (v1 > 0.f ? v1 : 0.2f*v1) * at4.y;
    float v2 = xv.z + xr4.z; v2 = (v2 > 0.f ? v2 : 0.2f*v2) * at4.z;
    float v3 = xv.w + xr4.w; v3 = (v3 > 0.f ? v3 : 0.2f*v3) * at4.w;
    float sum = (v0 + v1) + (v2 + v3);
    sum += __shfl_xor_sync(0xffffffffu, sum, 1);
    sum += __shfl_xor_sync(0xffffffffu, sum, 2);
    sum += __shfl_xor_sync(0xffffffffu, sum, 4);   // per-head alpha (8-lane groups)
    float ex = __expf(sum);
    den += ex;
    acc.x += ex*xv.x; acc.y += ex*xv.y; acc.z += ex*xv.z; acc.w += ex*xv.w;
  }
  *(float4*)&sacc[w][lane*4] = acc;
  sden[w][lane] = den;
  __syncthreads();

  float a = sacc[0][t] + sacc[1][t] + sacc[2][t] + sacc[3][t];
  int h = t >> 5;
  float dn = sden[0][h*8] + sden[1][h*8] + sden[2][h*8] + sden[3][h*8];
  float cnt = (float)(re - rs + 1);
  tmp[t] = a / (dn * cnt) + cb[t];
  __syncthreads();

  // Linear HD->DD with all 128 threads: thread t -> output (t&31), k-chunk (t>>5)
  int oc = t & 31, kc = t >> 5;
  float po = 0.f;
  #pragma unroll
  for (int k = 0; k < 32; k++) po += tmp[kc*32 + k] * lw[oc*HD + kc*32 + k];
  spo[t] = po;
  __syncthreads();
  if (t < DD) {
    float o = lb[t] + spo[t] + spo[t+32] + spo[t+64] + spo[t+96];
    if (do_pool) atomicMaxF(&g_pool[g_batch[d]*DD + t], o);
    else         outp[(size_t)d*DD + t] = o;
  }
}

// ---------------- head MLP ----------------
__global__ void k_final(const float* __restrict__ fc1W, const float* __restrict__ fc1b,
                        const float* __restrict__ fc2W, const float* __restrict__ fc2b,
                        float* __restrict__ out) {
  int g = threadIdx.x;
  if (g >= GG) return;
  float y[DD];
  #pragma unroll
  for (int j = 0; j < DD; j++) {
    float acc = fc1b[j];
    #pragma unroll
    for (int k = 0; k < DD; k++) acc += g_pool[g*DD + k] * fc1W[j*DD + k];
    y[j] = fmaxf(acc, 0.f);
  }
  #pragma unroll
  for (int i = 0; i < TT; i++) {
    float acc = fc2b[i];
    #pragma unroll
    for (int j = 0; j < DD; j++) acc += y[j] * fc2W[i*DD + j];
    out[g*TT + i] = acc;
  }
}

// ---------------- driver ----------------
extern "C" void kernel_launch(void* const* d_in, const int* in_sizes, int n_in,
                              void* d_out, int out_size) {
  const float* x   = (const float*)d_in[0];
  const void*  ei  = d_in[1];
  const void*  bt  = d_in[2];
  const float* Wl0 = (const float*)d_in[3];  const float* bl0 = (const float*)d_in[4];
  const float* Wr0 = (const float*)d_in[5];  const float* br0 = (const float*)d_in[6];
  const float* at0 = (const float*)d_in[7];  const float* cb0 = (const float*)d_in[8];
  const float* lw0 = (const float*)d_in[9];  const float* lb0 = (const float*)d_in[10];
  const float* Wl1 = (const float*)d_in[11]; const float* bl1 = (const float*)d_in[12];
  const float* Wr1 = (const float*)d_in[13]; const float* br1 = (const float*)d_in[14];
  const float* at1 = (const float*)d_in[15]; const float* cb1 = (const float*)d_in[16];
  const float* lw1 = (const float*)d_in[17]; const float* lb1 = (const float*)d_in[18];
  const float* f1W = (const float*)d_in[19]; const float* f1b = (const float*)d_in[20];
  const float* f2W = (const float*)d_in[21]; const float* f2b = (const float*)d_in[22];
  float* out = (float*)d_out;

  float *xlr, *hf;
  cudaGetSymbolAddress((void**)&xlr, g_xlr);
  cudaGetSymbolAddress((void**)&hf, g_hfeat);

  k_prep<<<(EE + 255)/256, 256>>>(ei, bt);
  k_count<<<(EE + 255)/256, 256>>>();
  k_scan<<<1, 1024>>>();
  k_fill<<<(EE + 255)/256, 256>>>();

  dim3 gg(2, (NN + 127)/128);
  k_dualgemm<<<gg, 256>>>(x,  Wl0, bl0, Wr0, br0, xlr, NN, FIN);
  k_conv_fused<<<NN, 128>>>(at0, cb0, lw0, lb0, hf, 0);
  k_dualgemm<<<gg, 256>>>(hf, Wl1, bl1, Wr1, br1, xlr, NN, DD);
  k_conv_fused<<<NN, 128>>>(at1, cb1, lw1, lb1, nullptr, 1);

  k_final<<<1, 128>>>(f1W, f1b, f2W, f2b, out);
}

// round 6
// speedup vs baseline: 2.3804x; 2.3804x over previous
#include <cuda_runtime.h>
#include <math.h>

#define NN 30000
#define EE 480000
#define FIN 128
#define DD 32
#define HH 4
#define HD 128
#define GG 128
#define TT 10

// ---------------- scratch (device globals; no allocation allowed) ----------------
__device__ float g_xlr[NN*256];     // per node: [0:128)=xl, [128:256)=xr
__device__ float g_hfeat[NN*DD];
__device__ int   g_src[EE];
__device__ int   g_dst[EE];
__device__ int   g_csr_src[EE];
__device__ int   g_deg[NN];         // zero at module load; re-zeroed by k_scan each run
__device__ int   g_fill[NN];
__device__ int   g_rowptr[NN+1];
__device__ int   g_batch[NN];
__device__ float g_pool[GG*DD];

// float atomic max via sign-split (correct incl. -0.0; init = -inf)
__device__ __forceinline__ void atomicMaxF(float* addr, float v) {
  unsigned u = __float_as_uint(v);
  if (u >> 31) atomicMin((unsigned*)addr, u);
  else         atomicMax((int*)addr, (int)u);
}

// ---------------- prep: dtype-agnostic index conversion + degree count + init ----------------
__global__ void k_prep(const void* __restrict__ ei, const void* __restrict__ bt) {
  __shared__ int s64;
  if (threadIdx.x == 0) {
    const long long* p = (const long long*)ei;
    int ok = 1;
    #pragma unroll
    for (int i = 0; i < 16; i++) { long long v = p[i]; if (v < 0 || v >= NN) ok = 0; }
    s64 = ok;
  }
  __syncthreads();
  int is64 = s64;
  int i = blockIdx.x*blockDim.x + threadIdx.x;
  if (i < EE) {
    int s, d;
    if (is64) {
      const long long* p = (const long long*)ei;
      s = (int)p[i]; d = (int)p[EE + i];
    } else {
      const int* p = (const int*)ei;
      s = p[i]; d = p[EE + i];
    }
    g_src[i] = s; g_dst[i] = d;
    atomicAdd(&g_deg[d], 1);            // g_deg zeroed by previous k_scan (or load-time)
  }
  if (i < NN)
    g_batch[i] = is64 ? (int)((const long long*)bt)[i] : ((const int*)bt)[i];
  if (i < GG*DD) g_pool[i] = -INFINITY;
}

// single-block exclusive scan over g_deg -> g_rowptr; seeds g_fill and re-zeroes g_deg
__global__ __launch_bounds__(1024) void k_scan() {
  __shared__ int ssum[1024];
  const int per = (NN + 1023)/1024;  // 30
  int t = threadIdx.x;
  int base = t*per;
  int vals[32];
  int local = 0;
  for (int i = 0; i < per; i++) {
    int idx = base + i;
    int v = 0;
    if (idx < NN) { v = g_deg[idx]; g_deg[idx] = 0; }   // zero for next replay
    vals[i] = local; local += v;
  }
  ssum[t] = local;
  __syncthreads();
  for (int off = 1; off < 1024; off <<= 1) {
    int v = (t >= off) ? ssum[t-off] : 0;
    __syncthreads();
    ssum[t] += v;
    __syncthreads();
  }
  int prev = (t == 0) ? 0 : ssum[t-1];
  for (int i = 0; i < per; i++) {
    int idx = base + i;
    if (idx < NN) { int rp = prev + vals[i]; g_rowptr[idx] = rp; g_fill[idx] = rp; }
  }
  if (t == 1023) g_rowptr[NN] = ssum[1023];
}

__global__ void k_fill() {
  int i = blockIdx.x*blockDim.x + threadIdx.x;
  if (i >= EE) return;
  int pos = atomicAdd(&g_fill[g_dst[i]], 1);
  g_csr_src[pos] = g_src[i];
}

// ---------------- dual SGEMM: C[m][0:128)=A@Wl^T+bl, C[m][128:256)=A@Wr^T+br ----------------
// BM=128, BN=128 (of combined 256), BK=16, 256 threads, 8x8 microtile.
__global__ __launch_bounds__(256) void k_dualgemm(
    const float* __restrict__ A,
    const float* __restrict__ Wl, const float* __restrict__ bl,
    const float* __restrict__ Wr, const float* __restrict__ br,
    float* __restrict__ C, int M, int K) {
  __shared__ float As[16][132];
  __shared__ float Bs[16][132];
  const int bm = blockIdx.y * 128;
  const int bn = blockIdx.x * 128;
  const int tid = threadIdx.x;
  const int tr = tid >> 4;
  const int tc = tid & 15;
  float acc[8][8] = {};
  for (int k0 = 0; k0 < K; k0 += 16) {
    #pragma unroll
    for (int i = 0; i < 2; i++) {
      int li = tid + i*256;
      int r = li >> 2;
      int kk = (li & 3) * 4;
      int m = bm + r;
      float4 v = make_float4(0.f,0.f,0.f,0.f);
      if (m < M) v = *(const float4*)&A[(size_t)m*K + k0 + kk];
      As[kk+0][r] = v.x; As[kk+1][r] = v.y; As[kk+2][r] = v.z; As[kk+3][r] = v.w;
    }
    #pragma unroll
    for (int i = 0; i < 2; i++) {
      int li = tid + i*256;
      int r = li >> 2;
      int kk = (li & 3) * 4;
      int n = bn + r;
      const float* Wrow = (n < 128) ? &Wl[(size_t)n*K] : &Wr[(size_t)(n-128)*K];
      float4 v = *(const float4*)&Wrow[k0 + kk];
      Bs[kk+0][r] = v.x; Bs[kk+1][r] = v.y; Bs[kk+2][r] = v.z; Bs[kk+3][r] = v.w;
    }
    __syncthreads();
    #pragma unroll
    for (int k = 0; k < 16; k++) {
      float4 a0 = *(const float4*)&As[k][tr*8];
      float4 a1 = *(const float4*)&As[k][tr*8 + 4];
      float4 b0 = *(const float4*)&Bs[k][tc*8];
      float4 b1 = *(const float4*)&Bs[k][tc*8 + 4];
      float a[8] = {a0.x,a0.y,a0.z,a0.w,a1.x,a1.y,a1.z,a1.w};
      float b[8] = {b0.x,b0.y,b0.z,b0.w,b1.x,b1.y,b1.z,b1.w};
      #pragma unroll
      for (int i = 0; i < 8; i++)
        #pragma unroll
        for (int j = 0; j < 8; j++) acc[i][j] += a[i]*b[j];
    }
    __syncthreads();
  }
  float bia[8];
  #pragma unroll
  for (int j = 0; j < 8; j++) {
    int n = bn + tc*8 + j;
    bia[j] = (n < 128) ? bl[n] : br[n-128];
  }
  #pragma unroll
  for (int i = 0; i < 8; i++) {
    int m = bm + tr*8 + i;
    if (m >= M) continue;
    float4 o0 = make_float4(acc[i][0]+bia[0], acc[i][1]+bia[1], acc[i][2]+bia[2], acc[i][3]+bia[3]);
    float4 o1 = make_float4(acc[i][4]+bia[4], acc[i][5]+bia[5], acc[i][6]+bia[6], acc[i][7]+bia[7]);
    *(float4*)&C[(size_t)m*256 + bn + tc*8]     = o0;
    *(float4*)&C[(size_t)m*256 + bn + tc*8 + 4] = o1;
  }
}

// ---------------- fused GATv2: warp-per-node edge gather + softmax + mean-agg + Linear ----------------
// 256 threads = 8 warps = 8 nodes per block. No __syncthreads anywhere; softmax
// denominator is warp-local (head = 8-lane group; alpha replicated via shfl_xor).
// exp without max-subtraction (softmax shift-invariant; alpha magnitudes are tiny here).
__global__ __launch_bounds__(256) void k_conv_fused(
    const float* __restrict__ att, const float* __restrict__ cb,
    const float* __restrict__ lw, const float* __restrict__ lb,
    float* __restrict__ outp, int do_pool) {
  __shared__ float stmp[8][132];
  int t = threadIdx.x;
  int w = t >> 5, lane = t & 31;
  int d = blockIdx.x*8 + w;
  if (d >= NN) return;

  float4 xr4 = *(const float4*)&g_xlr[(size_t)d*256 + 128 + lane*4];
  float4 at4 = *(const float4*)&att[lane*4];
  float4 acc = make_float4(0.f,0.f,0.f,0.f);
  float den = 0.f;
  int rs = __ldg(&g_rowptr[d]), re = __ldg(&g_rowptr[d+1]);
  int end = re + 1;                        // pos==re -> implicit self loop

  float4 xv_n;
  {
    int s0 = (rs < re) ? __ldg(&g_csr_src[rs]) : d;
    xv_n = *(const float4*)&g_xlr[(size_t)s0*256 + lane*4];
  }
  for (int pos = rs; pos < end; pos++) {
    float4 xv = xv_n;
    int pn = pos + 1;
    if (pn < end) {
      int sn = (pn < re) ? __ldg(&g_csr_src[pn]) : d;
      xv_n = *(const float4*)&g_xlr[(size_t)sn*256 + lane*4];
    }
    float v0 = xv.x + xr4.x; v0 = (v0 > 0.f ? v0 : 0.2f*v0) * at4.x;
    float v1 = xv.y + xr4.y; v1 = (v1 > 0.f ? v1 : 0.2f*v1) * at4.y;
    float v2 = xv.z + xr4.z; v2 = (v2 > 0.f ? v2 : 0.2f*v2) * at4.z;
    float v3 = xv.w + xr4.w; v3 = (v3 > 0.f ? v3 : 0.2f*v3) * at4.w;
    float sum = (v0 + v1) + (v2 + v3);
    sum += __shfl_xor_sync(0xffffffffu, sum, 1);
    sum += __shfl_xor_sync(0xffffffffu, sum, 2);
    sum += __shfl_xor_sync(0xffffffffu, sum, 4);   // per-head alpha in each 8-lane group
    float ex = __expf(sum);
    den += ex;
    acc.x += ex*xv.x; acc.y += ex*xv.y; acc.z += ex*xv.z; acc.w += ex*xv.w;
  }
  float inv = 1.0f / (den * (float)(re - rs + 1));
  float4 cb4 = *(const float4*)&cb[lane*4];
  stmp[w][lane*4+0] = acc.x*inv + cb4.x;
  stmp[w][lane*4+1] = acc.y*inv + cb4.y;
  stmp[w][lane*4+2] = acc.z*inv + cb4.z;
  stmp[w][lane*4+3] = acc.w*inv + cb4.w;
  __syncwarp();

  // Linear HD->DD: lane computes output feature `lane` (DD==32)
  float o = lb[lane];
  const float* lwr = &lw[(size_t)lane*HD];
  #pragma unroll
  for (int k = 0; k < HD; k += 4) {
    float4 wv = *(const float4*)&lwr[k];
    o += stmp[w][k+0]*wv.x + stmp[w][k+1]*wv.y + stmp[w][k+2]*wv.z + stmp[w][k+3]*wv.w;
  }
  if (do_pool) atomicMaxF(&g_pool[g_batch[d]*DD + lane], o);
  else         outp[(size_t)d*DD + lane] = o;
}

// ---------------- head MLP ----------------
__global__ void k_final(const float* __restrict__ fc1W, const float* __restrict__ fc1b,
                        const float* __restrict__ fc2W, const float* __restrict__ fc2b,
                        float* __restrict__ out) {
  int g = threadIdx.x;
  if (g >= GG) return;
  float y[DD];
  #pragma unroll
  for (int j = 0; j < DD; j++) {
    float acc = fc1b[j];
    #pragma unroll
    for (int k = 0; k < DD; k++) acc += g_pool[g*DD + k] * fc1W[j*DD + k];
    y[j] = fmaxf(acc, 0.f);
  }
  #pragma unroll
  for (int i = 0; i < TT; i++) {
    float acc = fc2b[i];
    #pragma unroll
    for (int j = 0; j < DD; j++) acc += y[j] * fc2W[i*DD + j];
    out[g*TT + i] = acc;
  }
}

// ---------------- driver ----------------
extern "C" void kernel_launch(void* const* d_in, const int* in_sizes, int n_in,
                              void* d_out, int out_size) {
  const float* x   = (const float*)d_in[0];
  const void*  ei  = d_in[1];
  const void*  bt  = d_in[2];
  const float* Wl0 = (const float*)d_in[3];  const float* bl0 = (const float*)d_in[4];
  const float* Wr0 = (const float*)d_in[5];  const float* br0 = (const float*)d_in[6];
  const float* at0 = (const float*)d_in[7];  const float* cb0 = (const float*)d_in[8];
  const float* lw0 = (const float*)d_in[9];  const float* lb0 = (const float*)d_in[10];
  const float* Wl1 = (const float*)d_in[11]; const float* bl1 = (const float*)d_in[12];
  const float* Wr1 = (const float*)d_in[13]; const float* br1 = (const float*)d_in[14];
  const float* at1 = (const float*)d_in[15]; const float* cb1 = (const float*)d_in[16];
  const float* lw1 = (const float*)d_in[17]; const float* lb1 = (const float*)d_in[18];
  const float* f1W = (const float*)d_in[19]; const float* f1b = (const float*)d_in[20];
  const float* f2W = (const float*)d_in[21]; const float* f2b = (const float*)d_in[22];
  float* out = (float*)d_out;

  float *xlr, *hf;
  cudaGetSymbolAddress((void**)&xlr, g_xlr);
  cudaGetSymbolAddress((void**)&hf, g_hfeat);

  k_prep<<<(EE + 255)/256, 256>>>(ei, bt);      // idx 0 (includes degree count)
  k_scan<<<1, 1024>>>();                        // idx 1
  k_fill<<<(EE + 255)/256, 256>>>();            // idx 2

  dim3 gg(2, (NN + 127)/128);
  k_dualgemm<<<gg, 256>>>(x,  Wl0, bl0, Wr0, br0, xlr, NN, FIN);   // idx 3 -> profiled
  k_conv_fused<<<(NN + 7)/8, 256>>>(at0, cb0, lw0, lb0, hf, 0);
  k_dualgemm<<<gg, 256>>>(hf, Wl1, bl1, Wr1, br1, xlr, NN, DD);
  k_conv_fused<<<(NN + 7)/8, 256>>>(at1, cb1, lw1, lb1, nullptr, 1);

  k_final<<<1, 128>>>(f1W, f1b, f2W, f2b, out);
}

// round 7
// speedup vs baseline: 2.4153x; 1.0147x over previous
#include <cuda_runtime.h>
#include <math.h>

#define NN 30000
#define EE 480000
#define FIN 128
#define DD 32
#define HH 4
#define HD 128
#define GG 128
#define TT 10
#define NGB 470           // gemm blocks: 2 * ceil(NN/128)

// ---------------- scratch (device globals; no allocation allowed) ----------------
__device__ float g_xlr[NN*256];     // per node: [0:128)=xl, [128:256)=xr
__device__ float g_hfeat[NN*DD];
__device__ int2  g_sd[EE];          // packed (src,dst)
__device__ int   g_csr_src[EE];
__device__ int   g_deg[NN];         // zero at load; re-zeroed by k_scan each run
__device__ int   g_fill[NN];
__device__ int   g_rowptr[NN+1];
__device__ int   g_batch[NN];
__device__ float g_pool[GG*DD];

// float atomic max via sign-split (correct incl. -0.0; init = -inf)
__device__ __forceinline__ void atomicMaxF(float* addr, float v) {
  unsigned u = __float_as_uint(v);
  if (u >> 31) atomicMin((unsigned*)addr, u);
  else         atomicMax((int*)addr, (int)u);
}

// ---------------- fused: dual SGEMM (blocks < NGB) + edge prep (blocks >= NGB) ----------------
// GEMM: C[m][0:128)=A@Wl^T+bl, C[m][128:256)=A@Wr^T+br. BM=128,BN=128,BK=16, 8x8 microtile.
// Prep: dtype-agnostic index conversion, degree count, batch copy, pool init.
__global__ __launch_bounds__(256) void k_gemm_prep(
    const float* __restrict__ A,
    const float* __restrict__ Wl, const float* __restrict__ bl,
    const float* __restrict__ Wr, const float* __restrict__ br,
    float* __restrict__ C, int M, int K,
    const void* __restrict__ ei, const void* __restrict__ bt) {
  if (blockIdx.x >= NGB) {                 // ---- prep branch ----
    __shared__ int s64;
    if (threadIdx.x == 0) {
      const long long* p = (const long long*)ei;
      int ok = 1;
      #pragma unroll
      for (int q = 0; q < 16; q++) { long long v = p[q]; if (v < 0 || v >= NN) ok = 0; }
      s64 = ok;
    }
    __syncthreads();
    int is64 = s64;
    int i = (blockIdx.x - NGB)*256 + threadIdx.x;
    if (i < EE) {
      int s, d;
      if (is64) {
        const long long* p = (const long long*)ei;
        s = (int)p[i]; d = (int)p[EE + i];
      } else {
        const int* p = (const int*)ei;
        s = p[i]; d = p[EE + i];
      }
      g_sd[i] = make_int2(s, d);
      atomicAdd(&g_deg[d], 1);
    }
    if (i < NN)
      g_batch[i] = is64 ? (int)((const long long*)bt)[i] : ((const int*)bt)[i];
    if (i < GG*DD) g_pool[i] = -INFINITY;
    return;
  }
  // ---- GEMM branch ----
  __shared__ float As[16][132];
  __shared__ float Bs[16][132];
  const int bm = (blockIdx.x >> 1) * 128;
  const int bn = (blockIdx.x & 1) * 128;
  const int tid = threadIdx.x;
  const int tr = tid >> 4;
  const int tc = tid & 15;
  float acc[8][8] = {};
  for (int k0 = 0; k0 < K; k0 += 16) {
    #pragma unroll
    for (int i = 0; i < 2; i++) {
      int li = tid + i*256;
      int r = li >> 2;
      int kk = (li & 3) * 4;
      int m = bm + r;
      float4 v = make_float4(0.f,0.f,0.f,0.f);
      if (m < M) v = *(const float4*)&A[(size_t)m*K + k0 + kk];
      As[kk+0][r] = v.x; As[kk+1][r] = v.y; As[kk+2][r] = v.z; As[kk+3][r] = v.w;
    }
    #pragma unroll
    for (int i = 0; i < 2; i++) {
      int li = tid + i*256;
      int r = li >> 2;
      int kk = (li & 3) * 4;
      int n = bn + r;
      const float* Wrow = (n < 128) ? &Wl[(size_t)n*K] : &Wr[(size_t)(n-128)*K];
      float4 v = *(const float4*)&Wrow[k0 + kk];
      Bs[kk+0][r] = v.x; Bs[kk+1][r] = v.y; Bs[kk+2][r] = v.z; Bs[kk+3][r] = v.w;
    }
    __syncthreads();
    #pragma unroll
    for (int k = 0; k < 16; k++) {
      float4 a0 = *(const float4*)&As[k][tr*8];
      float4 a1 = *(const float4*)&As[k][tr*8 + 4];
      float4 b0 = *(const float4*)&Bs[k][tc*8];
      float4 b1 = *(const float4*)&Bs[k][tc*8 + 4];
      float a[8] = {a0.x,a0.y,a0.z,a0.w,a1.x,a1.y,a1.z,a1.w};
      float b[8] = {b0.x,b0.y,b0.z,b0.w,b1.x,b1.y,b1.z,b1.w};
      #pragma unroll
      for (int i = 0; i < 8; i++)
        #pragma unroll
        for (int j = 0; j < 8; j++) acc[i][j] += a[i]*b[j];
    }
    __syncthreads();
  }
  float bia[8];
  #pragma unroll
  for (int j = 0; j < 8; j++) {
    int n = bn + tc*8 + j;
    bia[j] = (n < 128) ? bl[n] : br[n-128];
  }
  #pragma unroll
  for (int i = 0; i < 8; i++) {
    int m = bm + tr*8 + i;
    if (m >= M) continue;
    float4 o0 = make_float4(acc[i][0]+bia[0], acc[i][1]+bia[1], acc[i][2]+bia[2], acc[i][3]+bia[3]);
    float4 o1 = make_float4(acc[i][4]+bia[4], acc[i][5]+bia[5], acc[i][6]+bia[6], acc[i][7]+bia[7]);
    *(float4*)&C[(size_t)m*256 + bn + tc*8]     = o0;
    *(float4*)&C[(size_t)m*256 + bn + tc*8 + 4] = o1;
  }
}

// single-block exclusive scan over g_deg -> g_rowptr; seeds g_fill and re-zeroes g_deg
__global__ __launch_bounds__(1024) void k_scan() {
  __shared__ int ssum[1024];
  const int per = (NN + 1023)/1024;  // 30
  int t = threadIdx.x;
  int base = t*per;
  int vals[32];
  int local = 0;
  for (int i = 0; i < per; i++) {
    int idx = base + i;
    int v = 0;
    if (idx < NN) { v = g_deg[idx]; g_deg[idx] = 0; }   // zero for next replay
    vals[i] = local; local += v;
  }
  ssum[t] = local;
  __syncthreads();
  for (int off = 1; off < 1024; off <<= 1) {
    int v = (t >= off) ? ssum[t-off] : 0;
    __syncthreads();
    ssum[t] += v;
    __syncthreads();
  }
  int prev = (t == 0) ? 0 : ssum[t-1];
  for (int i = 0; i < per; i++) {
    int idx = base + i;
    if (idx < NN) { int rp = prev + vals[i]; g_rowptr[idx] = rp; g_fill[idx] = rp; }
  }
  if (t == 1023) g_rowptr[NN] = ssum[1023];
}

__global__ void k_fill() {
  int i = blockIdx.x*blockDim.x + threadIdx.x;
  if (i >= EE) return;
  int2 sd = g_sd[i];
  int pos = atomicAdd(&g_fill[sd.y], 1);
  g_csr_src[pos] = sd.x;
}

// ---------------- fused GATv2: warp-per-node, 3-stage pipelined edge loop ----------------
// 256 thr = 8 warps = 8 nodes/block. Head = 8-lane group; alpha via 3x shfl_xor.
// exp without max-subtraction (softmax shift-invariant; alpha magnitudes tiny here).
__global__ __launch_bounds__(256) void k_conv_fused(
    const float* __restrict__ att, const float* __restrict__ cb,
    const float* __restrict__ lw, const float* __restrict__ lb,
    float* __restrict__ outp, int do_pool) {
  __shared__ float stmp[8][132];
  int t = threadIdx.x;
  int w = t >> 5, lane = t & 31;
  int d = blockIdx.x*8 + w;
  if (d >= NN) return;

  float4 xr4 = *(const float4*)&g_xlr[(size_t)d*256 + 128 + lane*4];
  float4 at4 = *(const float4*)&att[lane*4];
  float4 acc = make_float4(0.f,0.f,0.f,0.f);
  float den = 0.f;
  int rs = __ldg(&g_rowptr[d]), re = __ldg(&g_rowptr[d+1]);
  int end = re + 1;                        // pos==re -> implicit self loop

  // 3-stage pipeline: index 2 ahead, features 1 ahead
  float4 xvA;                              // features for current pos
  int    sB = d;                           // index for pos+1
  {
    int s0 = (rs < re) ? __ldg(&g_csr_src[rs]) : d;
    xvA = *(const float4*)&g_xlr[(size_t)s0*256 + lane*4];
    if (rs + 1 < re) sB = __ldg(&g_csr_src[rs + 1]);
  }
  for (int pos = rs; pos < end; pos++) {
    float4 xv = xvA;
    if (pos + 1 < end)
      xvA = *(const float4*)&g_xlr[(size_t)sB*256 + lane*4];
    sB = (pos + 2 < re) ? __ldg(&g_csr_src[pos + 2]) : d;

    float v0 = xv.x + xr4.x; v0 = fmaxf(v0, 0.2f*v0) * at4.x;   // leaky_relu(0.2)
    float v1 = xv.y + xr4.y; v1 = fmaxf(v1, 0.2f*v1) * at4.y;
    float v2 = xv.z + xr4.z; v2 = fmaxf(v2, 0.2f*v2) * at4.z;
    float v3 = xv.w + xr4.w; v3 = fmaxf(v3, 0.2f*v3) * at4.w;
    float sum = (v0 + v1) + (v2 + v3);
    sum += __shfl_xor_sync(0xffffffffu, sum, 1);
    sum += __shfl_xor_sync(0xffffffffu, sum, 2);
    sum += __shfl_xor_sync(0xffffffffu, sum, 4);   // per-head alpha in each 8-lane group
    float ex = __expf(sum);
    den += ex;
    acc.x += ex*xv.x; acc.y += ex*xv.y; acc.z += ex*xv.z; acc.w += ex*xv.w;
  }
  float inv = 1.0f / (den * (float)(re - rs + 1));
  float4 cb4 = *(const float4*)&cb[lane*4];
  stmp[w][lane*4+0] = acc.x*inv + cb4.x;
  stmp[w][lane*4+1] = acc.y*inv + cb4.y;
  stmp[w][lane*4+2] = acc.z*inv + cb4.z;
  stmp[w][lane*4+3] = acc.w*inv + cb4.w;
  __syncwarp();

  // Linear HD->DD: lane computes output feature `lane` (DD==32)
  float o = lb[lane];
  const float* lwr = &lw[(size_t)lane*HD];
  #pragma unroll
  for (int k = 0; k < HD; k += 4) {
    float4 wv = *(const float4*)&lwr[k];
    o += stmp[w][k+0]*wv.x + stmp[w][k+1]*wv.y + stmp[w][k+2]*wv.z + stmp[w][k+3]*wv.w;
  }
  if (do_pool) atomicMaxF(&g_pool[g_batch[d]*DD + lane], o);
  else         outp[(size_t)d*DD + lane] = o;
}

// ---------------- head MLP ----------------
__global__ void k_final(const float* __restrict__ fc1W, const float* __restrict__ fc1b,
                        const float* __restrict__ fc2W, const float* __restrict__ fc2b,
                        float* __restrict__ out) {
  int g = threadIdx.x;
  if (g >= GG) return;
  float y[DD];
  #pragma unroll
  for (int j = 0; j < DD; j++) {
    float acc = fc1b[j];
    #pragma unroll
    for (int k = 0; k < DD; k++) acc += g_pool[g*DD + k] * fc1W[j*DD + k];
    y[j] = fmaxf(acc, 0.f);
  }
  #pragma unroll
  for (int i = 0; i < TT; i++) {
    float acc = fc2b[i];
    #pragma unroll
    for (int j = 0; j < DD; j++) acc += y[j] * fc2W[i*DD + j];
    out[g*TT + i] = acc;
  }
}

// ---------------- driver ----------------
extern "C" void kernel_launch(void* const* d_in, const int* in_sizes, int n_in,
                              void* d_out, int out_size) {
  const float* x   = (const float*)d_in[0];
  const void*  ei  = d_in[1];
  const void*  bt  = d_in[2];
  const float* Wl0 = (const float*)d_in[3];  const float* bl0 = (const float*)d_in[4];
  const float* Wr0 = (const float*)d_in[5];  const float* br0 = (const float*)d_in[6];
  const float* at0 = (const float*)d_in[7];  const float* cb0 = (const float*)d_in[8];
  const float* lw0 = (const float*)d_in[9];  const float* lb0 = (const float*)d_in[10];
  const float* Wl1 = (const float*)d_in[11]; const float* bl1 = (const float*)d_in[12];
  const float* Wr1 = (const float*)d_in[13]; const float* br1 = (const float*)d_in[14];
  const float* at1 = (const float*)d_in[15]; const float* cb1 = (const float*)d_in[16];
  const float* lw1 = (const float*)d_in[17]; const float* lb1 = (const float*)d_in[18];
  const float* f1W = (const float*)d_in[19]; const float* f1b = (const float*)d_in[20];
  const float* f2W = (const float*)d_in[21]; const float* f2b = (const float*)d_in[22];
  float* out = (float*)d_out;

  float *xlr, *hf;
  cudaGetSymbolAddress((void**)&xlr, g_xlr);
  cudaGetSymbolAddress((void**)&hf, g_hfeat);

  const int prep_blocks = (EE + 255)/256;           // 1875

  // idx 0: gemm0 + prep fused (independent work, overlapped)
  k_gemm_prep<<<NGB + prep_blocks, 256>>>(x, Wl0, bl0, Wr0, br0, xlr, NN, FIN, ei, bt);
  k_scan<<<1, 1024>>>();                            // idx 1
  k_fill<<<prep_blocks, 256>>>();                   // idx 2
  k_conv_fused<<<NN/8, 256>>>(at0, cb0, lw0, lb0, hf, 0);   // idx 3 -> profiled
  k_gemm_prep<<<NGB, 256>>>(hf, Wl1, bl1, Wr1, br1, xlr, NN, DD, ei, bt);  // idx 4
  k_conv_fused<<<NN/8, 256>>>(at1, cb1, lw1, lb1, nullptr, 1);             // idx 5
  k_final<<<1, 128>>>(f1W, f1b, f2W, f2b, out);     // idx 6
}

// round 8
// speedup vs baseline: 2.4846x; 1.0287x over previous
#include <cuda_runtime.h>
#include <cuda_fp16.h>
#include <math.h>

#define NN 30000
#define EE 480000
#define CSRN (EE + NN)      // csr with self loops appended per row
#define FIN 128
#define DD 32
#define HH 4
#define HD 128
#define GG 128
#define TT 10
#define NGB 470             // gemm blocks: 2 * ceil(NN/128)

// ---------------- scratch (device globals; no allocation allowed) ----------------
__device__ __half g_xlh[NN*HD];    // xl in fp16 (conv gather operand)
__device__ float  g_xr[NN*HD];     // xr in fp32
__device__ float  g_hfeat[NN*DD];
__device__ int2   g_sd[EE];        // packed (src,dst)
__device__ int    g_csr_src[CSRN];
__device__ int    g_deg[NN];       // zero at load; re-zeroed by k_scan each run
__device__ int    g_fill[NN];
__device__ int    g_rowptr[NN+1];  // self-loop-inclusive (shifted by +idx)
__device__ int    g_batch[NN];
__device__ float  g_pool[GG*DD];

// float atomic max via sign-split (correct incl. -0.0; init = -inf)
__device__ __forceinline__ void atomicMaxF(float* addr, float v) {
  unsigned u = __float_as_uint(v);
  if (u >> 31) atomicMin((unsigned*)addr, u);
  else         atomicMax((int*)addr, (int)u);
}

// ---------------- fused: dual SGEMM (blocks < NGB) + edge prep (blocks >= NGB) ----------------
// GEMM: xl[m] = A@Wl^T+bl (fp16 out), xr[m] = A@Wr^T+br (fp32 out).
// BM=128, BN=128 (bn: 0=xl half, 1=xr float), BK=16, 8x8 microtile.
__global__ __launch_bounds__(256) void k_gemm_prep(
    const float* __restrict__ A,
    const float* __restrict__ Wl, const float* __restrict__ bl,
    const float* __restrict__ Wr, const float* __restrict__ br,
    int M, int K,
    const void* __restrict__ ei, const void* __restrict__ bt) {
  if (blockIdx.x >= NGB) {                 // ---- prep branch ----
    __shared__ int s64;
    if (threadIdx.x == 0) {
      const long long* p = (const long long*)ei;
      int ok = 1;
      #pragma unroll
      for (int q = 0; q < 16; q++) { long long v = p[q]; if (v < 0 || v >= NN) ok = 0; }
      s64 = ok;
    }
    __syncthreads();
    int is64 = s64;
    int i = (blockIdx.x - NGB)*256 + threadIdx.x;
    if (i < EE) {
      int s, d;
      if (is64) {
        const long long* p = (const long long*)ei;
        s = (int)p[i]; d = (int)p[EE + i];
      } else {
        const int* p = (const int*)ei;
        s = p[i]; d = p[EE + i];
      }
      g_sd[i] = make_int2(s, d);
      atomicAdd(&g_deg[d], 1);
    }
    if (i < NN)
      g_batch[i] = is64 ? (int)((const long long*)bt)[i] : ((const int*)bt)[i];
    if (i < GG*DD) g_pool[i] = -INFINITY;
    return;
  }
  // ---- GEMM branch ----
  __shared__ float As[16][132];
  __shared__ float Bs[16][132];
  const int bm = (blockIdx.x >> 1) * 128;
  const int half_out = (blockIdx.x & 1) == 0;   // 0 -> xl(half), 1 -> xr(float)
  const int tid = threadIdx.x;
  const int tr = tid >> 4;
  const int tc = tid & 15;
  const float* W = half_out ? Wl : Wr;
  const float* bias = half_out ? bl : br;
  float acc[8][8] = {};
  for (int k0 = 0; k0 < K; k0 += 16) {
    #pragma unroll
    for (int i = 0; i < 2; i++) {
      int li = tid + i*256;
      int r = li >> 2;
      int kk = (li & 3) * 4;
      int m = bm + r;
      float4 v = make_float4(0.f,0.f,0.f,0.f);
      if (m < M) v = *(const float4*)&A[(size_t)m*K + k0 + kk];
      As[kk+0][r] = v.x; As[kk+1][r] = v.y; As[kk+2][r] = v.z; As[kk+3][r] = v.w;
    }
    #pragma unroll
    for (int i = 0; i < 2; i++) {
      int li = tid + i*256;
      int r = li >> 2;
      int kk = (li & 3) * 4;
      float4 v = *(const float4*)&W[(size_t)r*K + k0 + kk];
      Bs[kk+0][r] = v.x; Bs[kk+1][r] = v.y; Bs[kk+2][r] = v.z; Bs[kk+3][r] = v.w;
    }
    __syncthreads();
    #pragma unroll
    for (int k = 0; k < 16; k++) {
      float4 a0 = *(const float4*)&As[k][tr*8];
      float4 a1 = *(const float4*)&As[k][tr*8 + 4];
      float4 b0 = *(const float4*)&Bs[k][tc*8];
      float4 b1 = *(const float4*)&Bs[k][tc*8 + 4];
      float a[8] = {a0.x,a0.y,a0.z,a0.w,a1.x,a1.y,a1.z,a1.w};
      float b[8] = {b0.x,b0.y,b0.z,b0.w,b1.x,b1.y,b1.z,b1.w};
      #pragma unroll
      for (int i = 0; i < 8; i++)
        #pragma unroll
        for (int j = 0; j < 8; j++) acc[i][j] += a[i]*b[j];
    }
    __syncthreads();
  }
  float bia[8];
  #pragma unroll
  for (int j = 0; j < 8; j++) bia[j] = bias[tc*8 + j];
  #pragma unroll
  for (int i = 0; i < 8; i++) {
    int m = bm + tr*8 + i;
    if (m >= M) continue;
    if (half_out) {
      __half2 h[4];
      #pragma unroll
      for (int j = 0; j < 4; j++)
        h[j] = __floats2half2_rn(acc[i][2*j]+bia[2*j], acc[i][2*j+1]+bia[2*j+1]);
      *(uint4*)&g_xlh[(size_t)m*HD + tc*8] = *(uint4*)h;
    } else {
      float4 o0 = make_float4(acc[i][0]+bia[0], acc[i][1]+bia[1], acc[i][2]+bia[2], acc[i][3]+bia[3]);
      float4 o1 = make_float4(acc[i][4]+bia[4], acc[i][5]+bia[5], acc[i][6]+bia[6], acc[i][7]+bia[7]);
      *(float4*)&g_xr[(size_t)m*HD + tc*8]     = o0;
      *(float4*)&g_xr[(size_t)m*HD + tc*8 + 4] = o1;
    }
  }
}

// single-block exclusive scan over g_deg -> self-loop-inclusive g_rowptr; seeds g_fill; re-zeroes g_deg
__global__ __launch_bounds__(1024) void k_scan() {
  __shared__ int ssum[1024];
  const int per = (NN + 1023)/1024;  // 30
  int t = threadIdx.x;
  int base = t*per;
  int vals[32];
  int local = 0;
  for (int i = 0; i < per; i++) {
    int idx = base + i;
    int v = 0;
    if (idx < NN) { v = g_deg[idx]; g_deg[idx] = 0; }   // zero for next replay
    vals[i] = local; local += v;
  }
  ssum[t] = local;
  __syncthreads();
  for (int off = 1; off < 1024; off <<= 1) {
    int v = (t >= off) ? ssum[t-off] : 0;
    __syncthreads();
    ssum[t] += v;
    __syncthreads();
  }
  int prev = (t == 0) ? 0 : ssum[t-1];
  for (int i = 0; i < per; i++) {
    int idx = base + i;
    if (idx < NN) {
      int rp = prev + vals[i] + idx;     // +idx: one self-loop slot per preceding row
      g_rowptr[idx] = rp;
      g_fill[idx]   = rp;                // edges fill from row start
    }
  }
  if (t == 1023) g_rowptr[NN] = ssum[1023] + NN;
}

// fill CSR edges (atomic position) + write self-loop at end of each row
__global__ void k_fill() {
  int i = blockIdx.x*blockDim.x + threadIdx.x;
  if (i < EE) {
    int2 sd = g_sd[i];
    int pos = atomicAdd(&g_fill[sd.y], 1);
    g_csr_src[pos] = sd.x;
  }
  if (i < NN)
    g_csr_src[g_rowptr[i+1] - 1] = i;    // self loop (slot rowptr[i]+deg, no conflict)
}

// ---------------- fused GATv2: warp-per-node, fp16 gathers, pipelined ----------------
// 256 thr = 8 warps = 8 nodes/block. Lane holds features lane*4..+3; head = 8-lane group.
// exp without max-subtraction (softmax shift-invariant; alpha magnitudes tiny here).
__global__ __launch_bounds__(256) void k_conv_fused(
    const float* __restrict__ att, const float* __restrict__ cb,
    const float* __restrict__ lw, const float* __restrict__ lb,
    float* __restrict__ outp, int do_pool) {
  __shared__ float stmp[8][132];
  int t = threadIdx.x;
  int w = t >> 5, lane = t & 31;
  int d = blockIdx.x*8 + w;
  if (d >= NN) return;

  float4 xr4 = *(const float4*)&g_xr[(size_t)d*HD + lane*4];
  float4 at4 = *(const float4*)&att[lane*4];
  float4 acc = make_float4(0.f,0.f,0.f,0.f);
  float den = 0.f;
  int rs = __ldg(&g_rowptr[d]), re = __ldg(&g_rowptr[d+1]);  // always >= 1 entry (self)

  // pipeline: features 1 ahead, index 2 ahead (clamped)
  int s2;
  uint2 hN;
  {
    int s0 = __ldg(&g_csr_src[rs]);
    hN = *(const uint2*)&g_xlh[(size_t)s0*HD + lane*4];
    s2 = __ldg(&g_csr_src[(rs+1 < re) ? rs+1 : re-1]);
  }
  for (int pos = rs; pos < re; pos++) {
    uint2 hv = hN;
    int s3 = __ldg(&g_csr_src[(pos+2 < re) ? pos+2 : re-1]);
    if (pos + 1 < re)
      hN = *(const uint2*)&g_xlh[(size_t)s2*HD + lane*4];
    s2 = s3;

    float2 f01 = __half22float2(*(const __half2*)&hv.x);
    float2 f23 = __half22float2(*(const __half2*)&hv.y);
    float v0 = f01.x + xr4.x; v0 = fmaxf(v0, 0.2f*v0) * at4.x;   // leaky_relu(0.2)
    float v1 = f01.y + xr4.y; v1 = fmaxf(v1, 0.2f*v1) * at4.y;
    float v2 = f23.x + xr4.z; v2 = fmaxf(v2, 0.2f*v2) * at4.z;
    float v3 = f23.y + xr4.w; v3 = fmaxf(v3, 0.2f*v3) * at4.w;
    float sum = (v0 + v1) + (v2 + v3);
    sum += __shfl_xor_sync(0xffffffffu, sum, 1);
    sum += __shfl_xor_sync(0xffffffffu, sum, 2);
    sum += __shfl_xor_sync(0xffffffffu, sum, 4);   // per-head alpha in each 8-lane group
    float ex = __expf(sum);
    den += ex;
    acc.x += ex*f01.x; acc.y += ex*f01.y; acc.z += ex*f23.x; acc.w += ex*f23.y;
  }
  float inv = 1.0f / (den * (float)(re - rs));     // mean over deg+1 (self incl.)
  float4 cb4 = *(const float4*)&cb[lane*4];
  stmp[w][lane*4+0] = acc.x*inv + cb4.x;
  stmp[w][lane*4+1] = acc.y*inv + cb4.y;
  stmp[w][lane*4+2] = acc.z*inv + cb4.z;
  stmp[w][lane*4+3] = acc.w*inv + cb4.w;
  __syncwarp();

  // Linear HD->DD: lane computes output feature `lane` (DD==32)
  float o = lb[lane];
  const float* lwr = &lw[(size_t)lane*HD];
  #pragma unroll
  for (int k = 0; k < HD; k += 4) {
    float4 wv = *(const float4*)&lwr[k];
    o += stmp[w][k+0]*wv.x + stmp[w][k+1]*wv.y + stmp[w][k+2]*wv.z + stmp[w][k+3]*wv.w;
  }
  if (do_pool) atomicMaxF(&g_pool[g_batch[d]*DD + lane], o);
  else         outp[(size_t)d*DD + lane] = o;
}

// ---------------- head MLP ----------------
__global__ void k_final(const float* __restrict__ fc1W, const float* __restrict__ fc1b,
                        const float* __restrict__ fc2W, const float* __restrict__ fc2b,
                        float* __restrict__ out) {
  int g = threadIdx.x;
  if (g >= GG) return;
  float y[DD];
  #pragma unroll
  for (int j = 0; j < DD; j++) {
    float acc = fc1b[j];
    #pragma unroll
    for (int k = 0; k < DD; k++) acc += g_pool[g*DD + k] * fc1W[j*DD + k];
    y[j] = fmaxf(acc, 0.f);
  }
  #pragma unroll
  for (int i = 0; i < TT; i++) {
    float acc = fc2b[i];
    #pragma unroll
    for (int j = 0; j < DD; j++) acc += y[j] * fc2W[i*DD + j];
    out[g*TT + i] = acc;
  }
}

// ---------------- driver ----------------
extern "C" void kernel_launch(void* const* d_in, const int* in_sizes, int n_in,
                              void* d_out, int out_size) {
  const float* x   = (const float*)d_in[0];
  const void*  ei  = d_in[1];
  const void*  bt  = d_in[2];
  const float* Wl0 = (const float*)d_in[3];  const float* bl0 = (const float*)d_in[4];
  const float* Wr0 = (const float*)d_in[5];  const float* br0 = (const float*)d_in[6];
  const float* at0 = (const float*)d_in[7];  const float* cb0 = (const float*)d_in[8];
  const float* lw0 = (const float*)d_in[9];  const float* lb0 = (const float*)d_in[10];
  const float* Wl1 = (const float*)d_in[11]; const float* bl1 = (const float*)d_in[12];
  const float* Wr1 = (const float*)d_in[13]; const float* br1 = (const float*)d_in[14];
  const float* at1 = (const float*)d_in[15]; const float* cb1 = (const float*)d_in[16];
  const float* lw1 = (const float*)d_in[17]; const float* lb1 = (const float*)d_in[18];
  const float* f1W = (const float*)d_in[19]; const float* f1b = (const float*)d_in[20];
  const float* f2W = (const float*)d_in[21]; const float* f2b = (const float*)d_in[22];
  float* out = (float*)d_out;

  float* hf;
  cudaGetSymbolAddress((void**)&hf, g_hfeat);

  const int prep_blocks = (EE + 255)/256;           // 1875

  // idx 0: gemm0 + prep fused (independent work, overlapped)
  k_gemm_prep<<<NGB + prep_blocks, 256>>>(x, Wl0, bl0, Wr0, br0, NN, FIN, ei, bt);
  k_scan<<<1, 1024>>>();                            // idx 1
  k_fill<<<prep_blocks, 256>>>();                   // idx 2
  k_conv_fused<<<NN/8, 256>>>(at0, cb0, lw0, lb0, hf, 0);   // idx 3 -> profiled
  k_gemm_prep<<<NGB, 256>>>(hf, Wl1, bl1, Wr1, br1, NN, DD, ei, bt);  // idx 4
  k_conv_fused<<<NN/8, 256>>>(at1, cb1, lw1, lb1, nullptr, 1);        // idx 5
  k_final<<<1, 128>>>(f1W, f1b, f2W, f2b, out);     // idx 6
}

// round 9
// speedup vs baseline: 2.4957x; 1.0045x over previous
#include <cuda_runtime.h>
#include <cuda_fp16.h>
#include <math.h>

#define NN 30000
#define EE 480000
#define CSRN (EE + NN)      // csr with self loops appended per row
#define FIN 128
#define DD 32
#define HH 4
#define HD 128
#define GG 128
#define TT 10
#define NGB 470             // gemm blocks: 2 * ceil(NN/128)

// ---------------- scratch (device globals; no allocation allowed) ----------------
__device__ __half g_xlh[NN*HD];    // xl in fp16 (conv gather operand)
__device__ float  g_xr[NN*HD];     // xr in fp32
__device__ float  g_hfeat[NN*DD];
__device__ int2   g_sd[EE];        // packed (src,dst)
__device__ int    g_csr_src[CSRN];
__device__ int    g_deg[NN];       // zero at load; re-zeroed by k_scan each run
__device__ int    g_fill[NN];
__device__ int    g_rowptr[NN+1];  // self-loop-inclusive (shifted by +idx)
__device__ int    g_batch[NN];
__device__ float  g_pool[GG*DD];

// float atomic max via sign-split (correct incl. -0.0; init = -inf)
__device__ __forceinline__ void atomicMaxF(float* addr, float v) {
  unsigned u = __float_as_uint(v);
  if (u >> 31) atomicMin((unsigned*)addr, u);
  else         atomicMax((int*)addr, (int)u);
}

// ---------------- fused: dual SGEMM (blocks < NGB) + edge prep (blocks >= NGB) ----------------
__global__ __launch_bounds__(256) void k_gemm_prep(
    const float* __restrict__ A,
    const float* __restrict__ Wl, const float* __restrict__ bl,
    const float* __restrict__ Wr, const float* __restrict__ br,
    int M, int K,
    const void* __restrict__ ei, const void* __restrict__ bt) {
  if (blockIdx.x >= NGB) {                 // ---- prep branch ----
    __shared__ int s64;
    if (threadIdx.x == 0) {
      const long long* p = (const long long*)ei;
      int ok = 1;
      #pragma unroll
      for (int q = 0; q < 16; q++) { long long v = p[q]; if (v < 0 || v >= NN) ok = 0; }
      s64 = ok;
    }
    __syncthreads();
    int is64 = s64;
    int i = (blockIdx.x - NGB)*256 + threadIdx.x;
    if (i < EE) {
      int s, d;
      if (is64) {
        const long long* p = (const long long*)ei;
        s = (int)p[i]; d = (int)p[EE + i];
      } else {
        const int* p = (const int*)ei;
        s = p[i]; d = p[EE + i];
      }
      g_sd[i] = make_int2(s, d);
      atomicAdd(&g_deg[d], 1);
    }
    if (i < NN)
      g_batch[i] = is64 ? (int)((const long long*)bt)[i] : ((const int*)bt)[i];
    if (i < GG*DD) g_pool[i] = -INFINITY;
    return;
  }
  // ---- GEMM branch ----
  __shared__ float As[16][132];
  __shared__ float Bs[16][132];
  const int bm = (blockIdx.x >> 1) * 128;
  const int half_out = (blockIdx.x & 1) == 0;   // 0 -> xl(half), 1 -> xr(float)
  const int tid = threadIdx.x;
  const int tr = tid >> 4;
  const int tc = tid & 15;
  const float* W = half_out ? Wl : Wr;
  const float* bias = half_out ? bl : br;
  float acc[8][8] = {};
  for (int k0 = 0; k0 < K; k0 += 16) {
    #pragma unroll
    for (int i = 0; i < 2; i++) {
      int li = tid + i*256;
      int r = li >> 2;
      int kk = (li & 3) * 4;
      int m = bm + r;
      float4 v = make_float4(0.f,0.f,0.f,0.f);
      if (m < M) v = *(const float4*)&A[(size_t)m*K + k0 + kk];
      As[kk+0][r] = v.x; As[kk+1][r] = v.y; As[kk+2][r] = v.z; As[kk+3][r] = v.w;
    }
    #pragma unroll
    for (int i = 0; i < 2; i++) {
      int li = tid + i*256;
      int r = li >> 2;
      int kk = (li & 3) * 4;
      float4 v = *(const float4*)&W[(size_t)r*K + k0 + kk];
      Bs[kk+0][r] = v.x; Bs[kk+1][r] = v.y; Bs[kk+2][r] = v.z; Bs[kk+3][r] = v.w;
    }
    __syncthreads();
    #pragma unroll
    for (int k = 0; k < 16; k++) {
      float4 a0 = *(const float4*)&As[k][tr*8];
      float4 a1 = *(const float4*)&As[k][tr*8 + 4];
      float4 b0 = *(const float4*)&Bs[k][tc*8];
      float4 b1 = *(const float4*)&Bs[k][tc*8 + 4];
      float a[8] = {a0.x,a0.y,a0.z,a0.w,a1.x,a1.y,a1.z,a1.w};
      float b[8] = {b0.x,b0.y,b0.z,b0.w,b1.x,b1.y,b1.z,b1.w};
      #pragma unroll
      for (int i = 0; i < 8; i++)
        #pragma unroll
        for (int j = 0; j < 8; j++) acc[i][j] += a[i]*b[j];
    }
    __syncthreads();
  }
  float bia[8];
  #pragma unroll
  for (int j = 0; j < 8; j++) bia[j] = bias[tc*8 + j];
  #pragma unroll
  for (int i = 0; i < 8; i++) {
    int m = bm + tr*8 + i;
    if (m >= M) continue;
    if (half_out) {
      __half2 h[4];
      #pragma unroll
      for (int j = 0; j < 4; j++)
        h[j] = __floats2half2_rn(acc[i][2*j]+bia[2*j], acc[i][2*j+1]+bia[2*j+1]);
      *(uint4*)&g_xlh[(size_t)m*HD + tc*8] = *(uint4*)h;
    } else {
      float4 o0 = make_float4(acc[i][0]+bia[0], acc[i][1]+bia[1], acc[i][2]+bia[2], acc[i][3]+bia[3]);
      float4 o1 = make_float4(acc[i][4]+bia[4], acc[i][5]+bia[5], acc[i][6]+bia[6], acc[i][7]+bia[7]);
      *(float4*)&g_xr[(size_t)m*HD + tc*8]     = o0;
      *(float4*)&g_xr[(size_t)m*HD + tc*8 + 4] = o1;
    }
  }
}

// single-block exclusive scan over g_deg -> self-loop-inclusive g_rowptr; seeds g_fill; re-zeroes g_deg
__global__ __launch_bounds__(1024) void k_scan() {
  __shared__ int ssum[1024];
  const int per = (NN + 1023)/1024;  // 30
  int t = threadIdx.x;
  int base = t*per;
  int vals[32];
  int local = 0;
  for (int i = 0; i < per; i++) {
    int idx = base + i;
    int v = 0;
    if (idx < NN) { v = g_deg[idx]; g_deg[idx] = 0; }   // zero for next replay
    vals[i] = local; local += v;
  }
  ssum[t] = local;
  __syncthreads();
  for (int off = 1; off < 1024; off <<= 1) {
    int v = (t >= off) ? ssum[t-off] : 0;
    __syncthreads();
    ssum[t] += v;
    __syncthreads();
  }
  int prev = (t == 0) ? 0 : ssum[t-1];
  for (int i = 0; i < per; i++) {
    int idx = base + i;
    if (idx < NN) {
      int rp = prev + vals[i] + idx;     // +idx: one self-loop slot per preceding row
      g_rowptr[idx] = rp;
      g_fill[idx]   = rp;                // edges fill from row start
    }
  }
  if (t == 1023) g_rowptr[NN] = ssum[1023] + NN;
}

// fill CSR edges (atomic position) + write self-loop at end of each row
__global__ void k_fill() {
  int i = blockIdx.x*blockDim.x + threadIdx.x;
  if (i < EE) {
    int2 sd = g_sd[i];
    int pos = atomicAdd(&g_fill[sd.y], 1);
    g_csr_src[pos] = sd.x;
  }
  if (i < NN)
    g_csr_src[g_rowptr[i+1] - 1] = i;    // self loop (slot rowptr[i]+deg, no conflict)
}

// ---------------- fused GATv2: warp-per-node, 4-edge batched ILP ----------------
// 256 thr = 8 warps = 8 nodes/block. Lane holds features lane*4..+3; head = 8-lane group.
// Main loop processes 4 edges/iteration: 4 independent gathers in flight, 4 interleaved
// shuffle-reduction chains. exp without max-subtraction (softmax shift-invariant).
__global__ __launch_bounds__(256) void k_conv_fused(
    const float* __restrict__ att, const float* __restrict__ cb,
    const float* __restrict__ lw, const float* __restrict__ lb,
    float* __restrict__ outp, int do_pool) {
  __shared__ float stmp[8][132];
  int t = threadIdx.x;
  int w = t >> 5, lane = t & 31;
  int d = blockIdx.x*8 + w;
  if (d >= NN) return;

  float4 xr4 = *(const float4*)&g_xr[(size_t)d*HD + lane*4];
  float4 at4 = *(const float4*)&att[lane*4];
  float4 acc = make_float4(0.f,0.f,0.f,0.f);
  float den = 0.f;
  int rs = __ldg(&g_rowptr[d]), re = __ldg(&g_rowptr[d+1]);  // always >= 1 entry (self)

  int pos = rs;
  for (; pos + 4 <= re; pos += 4) {
    int s0 = __ldg(&g_csr_src[pos+0]);
    int s1 = __ldg(&g_csr_src[pos+1]);
    int s2 = __ldg(&g_csr_src[pos+2]);
    int s3 = __ldg(&g_csr_src[pos+3]);
    uint2 hq[4];
    hq[0] = *(const uint2*)&g_xlh[(size_t)s0*HD + lane*4];
    hq[1] = *(const uint2*)&g_xlh[(size_t)s1*HD + lane*4];
    hq[2] = *(const uint2*)&g_xlh[(size_t)s2*HD + lane*4];
    hq[3] = *(const uint2*)&g_xlh[(size_t)s3*HD + lane*4];
    float2 f01[4], f23[4];
    float sum[4];
    #pragma unroll
    for (int q = 0; q < 4; q++) {
      f01[q] = __half22float2(*(const __half2*)&hq[q].x);
      f23[q] = __half22float2(*(const __half2*)&hq[q].y);
      float v0 = f01[q].x + xr4.x; v0 = fmaxf(v0, 0.2f*v0) * at4.x;
      float v1 = f01[q].y + xr4.y; v1 = fmaxf(v1, 0.2f*v1) * at4.y;
      float v2 = f23[q].x + xr4.z; v2 = fmaxf(v2, 0.2f*v2) * at4.z;
      float v3 = f23[q].y + xr4.w; v3 = fmaxf(v3, 0.2f*v3) * at4.w;
      sum[q] = (v0 + v1) + (v2 + v3);
    }
    #pragma unroll
    for (int q = 0; q < 4; q++) sum[q] += __shfl_xor_sync(0xffffffffu, sum[q], 1);
    #pragma unroll
    for (int q = 0; q < 4; q++) sum[q] += __shfl_xor_sync(0xffffffffu, sum[q], 2);
    #pragma unroll
    for (int q = 0; q < 4; q++) sum[q] += __shfl_xor_sync(0xffffffffu, sum[q], 4);
    #pragma unroll
    for (int q = 0; q < 4; q++) {
      float ex = __expf(sum[q]);
      den += ex;
      acc.x += ex*f01[q].x; acc.y += ex*f01[q].y;
      acc.z += ex*f23[q].x; acc.w += ex*f23[q].y;
    }
  }
  for (; pos < re; pos++) {
    int s = __ldg(&g_csr_src[pos]);
    uint2 hv = *(const uint2*)&g_xlh[(size_t)s*HD + lane*4];
    float2 f01 = __half22float2(*(const __half2*)&hv.x);
    float2 f23 = __half22float2(*(const __half2*)&hv.y);
    float v0 = f01.x + xr4.x; v0 = fmaxf(v0, 0.2f*v0) * at4.x;
    float v1 = f01.y + xr4.y; v1 = fmaxf(v1, 0.2f*v1) * at4.y;
    float v2 = f23.x + xr4.z; v2 = fmaxf(v2, 0.2f*v2) * at4.z;
    float v3 = f23.y + xr4.w; v3 = fmaxf(v3, 0.2f*v3) * at4.w;
    float sum = (v0 + v1) + (v2 + v3);
    sum += __shfl_xor_sync(0xffffffffu, sum, 1);
    sum += __shfl_xor_sync(0xffffffffu, sum, 2);
    sum += __shfl_xor_sync(0xffffffffu, sum, 4);
    float ex = __expf(sum);
    den += ex;
    acc.x += ex*f01.x; acc.y += ex*f01.y; acc.z += ex*f23.x; acc.w += ex*f23.y;
  }

  float inv = 1.0f / (den * (float)(re - rs));     // mean over deg+1 (self incl.)
  float4 cb4 = *(const float4*)&cb[lane*4];
  stmp[w][lane*4+0] = acc.x*inv + cb4.x;
  stmp[w][lane*4+1] = acc.y*inv + cb4.y;
  stmp[w][lane*4+2] = acc.z*inv + cb4.z;
  stmp[w][lane*4+3] = acc.w*inv + cb4.w;
  __syncwarp();

  // Linear HD->DD: lane computes output feature `lane` (DD==32)
  float o = lb[lane];
  const float* lwr = &lw[(size_t)lane*HD];
  #pragma unroll
  for (int k = 0; k < HD; k += 4) {
    float4 wv = *(const float4*)&lwr[k];
    o += stmp[w][k+0]*wv.x + stmp[w][k+1]*wv.y + stmp[w][k+2]*wv.z + stmp[w][k+3]*wv.w;
  }
  if (do_pool) atomicMaxF(&g_pool[g_batch[d]*DD + lane], o);
  else         outp[(size_t)d*DD + lane] = o;
}

// ---------------- head MLP ----------------
__global__ void k_final(const float* __restrict__ fc1W, const float* __restrict__ fc1b,
                        const float* __restrict__ fc2W, const float* __restrict__ fc2b,
                        float* __restrict__ out) {
  int g = threadIdx.x;
  if (g >= GG) return;
  float y[DD];
  #pragma unroll
  for (int j = 0; j < DD; j++) {
    float acc = fc1b[j];
    #pragma unroll
    for (int k = 0; k < DD; k++) acc += g_pool[g*DD + k] * fc1W[j*DD + k];
    y[j] = fmaxf(acc, 0.f);
  }
  #pragma unroll
  for (int i = 0; i < TT; i++) {
    float acc = fc2b[i];
    #pragma unroll
    for (int j = 0; j < DD; j++) acc += y[j] * fc2W[i*DD + j];
    out[g*TT + i] = acc;
  }
}

// ---------------- driver ----------------
extern "C" void kernel_launch(void* const* d_in, const int* in_sizes, int n_in,
                              void* d_out, int out_size) {
  const float* x   = (const float*)d_in[0];
  const void*  ei  = d_in[1];
  const void*  bt  = d_in[2];
  const float* Wl0 = (const float*)d_in[3];  const float* bl0 = (const float*)d_in[4];
  const float* Wr0 = (const float*)d_in[5];  const float* br0 = (const float*)d_in[6];
  const float* at0 = (const float*)d_in[7];  const float* cb0 = (const float*)d_in[8];
  const float* lw0 = (const float*)d_in[9];  const float* lb0 = (const float*)d_in[10];
  const float* Wl1 = (const float*)d_in[11]; const float* bl1 = (const float*)d_in[12];
  const float* Wr1 = (const float*)d_in[13]; const float* br1 = (const float*)d_in[14];
  const float* at1 = (const float*)d_in[15]; const float* cb1 = (const float*)d_in[16];
  const float* lw1 = (const float*)d_in[17]; const float* lb1 = (const float*)d_in[18];
  const float* f1W = (const float*)d_in[19]; const float* f1b = (const float*)d_in[20];
  const float* f2W = (const float*)d_in[21]; const float* f2b = (const float*)d_in[22];
  float* out = (float*)d_out;

  float* hf;
  cudaGetSymbolAddress((void**)&hf, g_hfeat);

  const int prep_blocks = (EE + 255)/256;           // 1875

  // idx 0: gemm0 + prep fused (independent work, overlapped)
  k_gemm_prep<<<NGB + prep_blocks, 256>>>(x, Wl0, bl0, Wr0, br0, NN, FIN, ei, bt);
  k_scan<<<1, 1024>>>();                            // idx 1
  k_fill<<<prep_blocks, 256>>>();                   // idx 2
  k_conv_fused<<<NN/8, 256>>>(at0, cb0, lw0, lb0, hf, 0);   // idx 3 -> profiled
  k_gemm_prep<<<NGB, 256>>>(hf, Wl1, bl1, Wr1, br1, NN, DD, ei, bt);  // idx 4
  k_conv_fused<<<NN/8, 256>>>(at1, cb1, lw1, lb1, nullptr, 1);        // idx 5
  k_final<<<1, 128>>>(f1W, f1b, f2W, f2b, out);     // idx 6
}